// round 1
// baseline (speedup 1.0000x reference)
#include <cuda_runtime.h>
#include <math.h>

#define BATCH 16
#define HID   512
#define NN    2048

// Scratch (allocation-free rule: __device__ globals)
__device__ float g_d[BATCH * NN];   // d[b,m] = rsqrt(rowsum)
__device__ float g_w[BATCH * NN];   // w[b,m] = d[b,0]*ahat[b,0,m]*d[b,m]
__device__ float g_y[BATCH * HID];  // y[b,h] = sum_m w[b,m]*feat[b,h,m]

// ---------------------------------------------------------------------------
// Kernel 1: per-row sums of clip(adj,0) + 1 (diagonal), store rsqrt.
// One warp per row (2048 floats = 16 x float4 per lane-stride loop).
// ---------------------------------------------------------------------------
__global__ void rowsum_kernel(const float* __restrict__ adj) {
    int warp = (blockIdx.x * blockDim.x + threadIdx.x) >> 5;
    int lane = threadIdx.x & 31;
    if (warp >= BATCH * NN) return;

    const float4* row = (const float4*)(adj + (size_t)warp * NN);
    float s = 0.f;
#pragma unroll
    for (int i = 0; i < NN / (4 * 32); ++i) {
        float4 v = row[lane + i * 32];
        s += fmaxf(v.x, 0.f) + fmaxf(v.y, 0.f) + fmaxf(v.z, 0.f) + fmaxf(v.w, 0.f);
    }
#pragma unroll
    for (int o = 16; o; o >>= 1) s += __shfl_xor_sync(0xffffffffu, s, o);
    if (lane == 0) g_d[warp] = rsqrtf(s + 1.0f);  // +1 from identity diagonal
}

// ---------------------------------------------------------------------------
// Kernel 2 (tiny): w[b,m] = d[b,0] * (clip(adj[b,0,m],0) + [m==0]) * d[b,m]
// ---------------------------------------------------------------------------
__global__ void weight_kernel(const float* __restrict__ adj) {
    int idx = blockIdx.x * blockDim.x + threadIdx.x;
    if (idx >= BATCH * NN) return;
    int b = idx / NN;
    int m = idx - b * NN;
    float a = fmaxf(adj[(size_t)b * NN * NN + m], 0.f) + (m == 0 ? 1.0f : 0.0f);
    g_w[idx] = g_d[b * NN] * a * g_d[idx];
}

// ---------------------------------------------------------------------------
// Kernel 3: y[b,h] = dot(w[b,:], feat[b,h,:]). One warp per (b,h).
// feat is [B, H, N] with n contiguous -> fully coalesced float4 loads.
// w row (8 KB) is reused by 512 warps per batch -> L2-resident.
// ---------------------------------------------------------------------------
__global__ void reduce_kernel(const float* __restrict__ feat) {
    int warp = (blockIdx.x * blockDim.x + threadIdx.x) >> 5;
    int lane = threadIdx.x & 31;
    if (warp >= BATCH * HID) return;
    int b = warp / HID;

    const float4* f  = (const float4*)(feat + (size_t)warp * NN);
    const float4* wp = (const float4*)(g_w + b * NN);
    float s = 0.f;
#pragma unroll
    for (int i = 0; i < NN / (4 * 32); ++i) {
        float4 fv = f[lane + i * 32];
        float4 wv = wp[lane + i * 32];
        s += fv.x * wv.x + fv.y * wv.y + fv.z * wv.z + fv.w * wv.w;
    }
#pragma unroll
    for (int o = 16; o; o >>= 1) s += __shfl_xor_sync(0xffffffffu, s, o);
    if (lane == 0) g_y[warp] = s;
}

// ---------------------------------------------------------------------------
// Kernel 4: out[b,k] = tanh( sum_h y[b,h]*W[h,k] + bias[b,k] )
// One block per batch, 512 threads (one per k). W rows read coalesced.
// 4 accumulators to break the FMA dependency chain.
// ---------------------------------------------------------------------------
__global__ void out_kernel(const float* __restrict__ Wmat,
                           const float* __restrict__ bias,
                           float* __restrict__ out) {
    __shared__ float ys[HID];
    int b = blockIdx.x;
    int k = threadIdx.x;
    ys[k] = g_y[b * HID + k];
    __syncthreads();

    float a0 = 0.f, a1 = 0.f, a2 = 0.f, a3 = 0.f;
#pragma unroll 4
    for (int h = 0; h < HID; h += 4) {
        a0 = fmaf(ys[h + 0], Wmat[(h + 0) * HID + k], a0);
        a1 = fmaf(ys[h + 1], Wmat[(h + 1) * HID + k], a1);
        a2 = fmaf(ys[h + 2], Wmat[(h + 2) * HID + k], a2);
        a3 = fmaf(ys[h + 3], Wmat[(h + 3) * HID + k], a3);
    }
    float acc = (a0 + a1) + (a2 + a3) + bias[b * HID + k];
    out[b * HID + k] = tanhf(acc);
}

// ---------------------------------------------------------------------------
extern "C" void kernel_launch(void* const* d_in, const int* in_sizes, int n_in,
                              void* d_out, int out_size) {
    const float* feat = (const float*)d_in[0];  // [B, H, N]
    const float* adj  = (const float*)d_in[1];  // [B, N, N]
    const float* Wm   = (const float*)d_in[2];  // [H, H]
    const float* bias = (const float*)d_in[3];  // [B, H]
    float* out = (float*)d_out;                 // [B, H]

    // K1: 32768 rows, 1 warp each, 256 thr/block -> 4096 blocks
    rowsum_kernel<<<(BATCH * NN) / 8, 256>>>(adj);
    // K2: 32768 elements
    weight_kernel<<<(BATCH * NN + 255) / 256, 256>>>(adj);
    // K3: 8192 (b,h) pairs, 1 warp each -> 1024 blocks
    reduce_kernel<<<(BATCH * HID) / 8, 256>>>(feat);
    // K4: 16 blocks x 512 threads
    out_kernel<<<BATCH, HID>>>(Wm, bias, out);
}

// round 5
// speedup vs baseline: 1.1753x; 1.1753x over previous
#include <cuda_runtime.h>
#include <math.h>

#define BATCH 16
#define HID   512
#define NN    2048
#define HCHUNKS 8
#define HPER    (HID / HCHUNKS)   // 64

// Scratch (allocation-free rule: __device__ globals)
__device__ float g_d[BATCH * NN];              // d[b,m] = rsqrt(rowsum)
__device__ float g_w[BATCH * NN];              // w[b,m]
__device__ float g_y[BATCH * HID];             // y[b,h]
__device__ float g_part[HCHUNKS * BATCH * HID]; // partial GEMV sums

// ---------------------------------------------------------------------------
// Kernel 1: per-row sums of clip(adj,0) (+1 diagonal), store rsqrt.
// One warp per row; fully-coalesced float4 loads, 16 independent loads/lane.
// ---------------------------------------------------------------------------
__global__ void rowsum_kernel(const float* __restrict__ adj) {
    int warp = (blockIdx.x * blockDim.x + threadIdx.x) >> 5;
    int lane = threadIdx.x & 31;
    if (warp >= BATCH * NN) return;

    const float4* row = (const float4*)(adj + (size_t)warp * NN);
    float s = 0.f;
#pragma unroll
    for (int i = 0; i < NN / (4 * 32); ++i) {
        float4 v = row[lane + i * 32];
        s += fmaxf(v.x, 0.f) + fmaxf(v.y, 0.f) + fmaxf(v.z, 0.f) + fmaxf(v.w, 0.f);
    }
#pragma unroll
    for (int o = 16; o; o >>= 1) s += __shfl_xor_sync(0xffffffffu, s, o);
    if (lane == 0) g_d[warp] = rsqrtf(s + 1.0f);
}

// ---------------------------------------------------------------------------
// Kernel 2 (tiny): w[b,m] = d[b,0] * (clip(adj[b,0,m],0) + [m==0]) * d[b,m]
// ---------------------------------------------------------------------------
__global__ void weight_kernel(const float* __restrict__ adj) {
    int idx = blockIdx.x * blockDim.x + threadIdx.x;
    if (idx >= BATCH * NN) return;
    int b = idx / NN;
    int m = idx - b * NN;
    float a = fmaxf(adj[(size_t)b * NN * NN + m], 0.f) + (m == 0 ? 1.0f : 0.0f);
    g_w[idx] = g_d[b * NN] * a * g_d[idx];
}

// ---------------------------------------------------------------------------
// Kernel 3: y[b,h] = dot(w[b,:], feat[b,h,:]). One warp per (b,h).
// ---------------------------------------------------------------------------
__global__ void reduce_kernel(const float* __restrict__ feat) {
    int warp = (blockIdx.x * blockDim.x + threadIdx.x) >> 5;
    int lane = threadIdx.x & 31;
    if (warp >= BATCH * HID) return;
    int b = warp / HID;

    const float4* f  = (const float4*)(feat + (size_t)warp * NN);
    const float4* wp = (const float4*)(g_w + b * NN);
    float s = 0.f;
#pragma unroll
    for (int i = 0; i < NN / (4 * 32); ++i) {
        float4 fv = f[lane + i * 32];
        float4 wv = wp[lane + i * 32];
        s += fv.x * wv.x + fv.y * wv.y + fv.z * wv.z + fv.w * wv.w;
    }
#pragma unroll
    for (int o = 16; o; o >>= 1) s += __shfl_xor_sync(0xffffffffu, s, o);
    if (lane == 0) g_y[warp] = s;
}

// ---------------------------------------------------------------------------
// Kernel 4a: partial GEMV. grid = (BATCH, HCHUNKS), 256 threads.
// Block (b, c) computes, for all 512 k (2 per thread):
//   part[c][b][k] = sum_{h in chunk c} y[b,h] * W[h,k]
// W reads are coalesced across k; h-loop unrolled with indep accumulators.
// ---------------------------------------------------------------------------
__global__ void gemv_part_kernel(const float* __restrict__ Wmat) {
    __shared__ float ys[HPER];
    int b = blockIdx.x;
    int c = blockIdx.y;
    int t = threadIdx.x;
    if (t < HPER) ys[t] = g_y[b * HID + c * HPER + t];
    __syncthreads();

    const float* Wb = Wmat + (size_t)(c * HPER) * HID;
#pragma unroll
    for (int rep = 0; rep < 2; ++rep) {
        int k = t + rep * 256;
        float a0 = 0.f, a1 = 0.f, a2 = 0.f, a3 = 0.f;
#pragma unroll 4
        for (int h = 0; h < HPER; h += 4) {
            a0 = fmaf(ys[h + 0], Wb[(h + 0) * HID + k], a0);
            a1 = fmaf(ys[h + 1], Wb[(h + 1) * HID + k], a1);
            a2 = fmaf(ys[h + 2], Wb[(h + 2) * HID + k], a2);
            a3 = fmaf(ys[h + 3], Wb[(h + 3) * HID + k], a3);
        }
        g_part[(c * BATCH + b) * HID + k] = (a0 + a1) + (a2 + a3);
    }
}

// ---------------------------------------------------------------------------
// Kernel 4b: sum the 8 partials + bias, tanh, write. 8192 threads.
// ---------------------------------------------------------------------------
__global__ void finish_kernel(const float* __restrict__ bias,
                              float* __restrict__ out) {
    int idx = blockIdx.x * blockDim.x + threadIdx.x;  // b*HID + k
    if (idx >= BATCH * HID) return;
    float acc = bias[idx];
#pragma unroll
    for (int c = 0; c < HCHUNKS; ++c)
        acc += g_part[c * (BATCH * HID) + idx];
    out[idx] = tanhf(acc);
}

// ---------------------------------------------------------------------------
extern "C" void kernel_launch(void* const* d_in, const int* in_sizes, int n_in,
                              void* d_out, int out_size) {
    const float* feat = (const float*)d_in[0];  // [B, H, N]
    const float* adj  = (const float*)d_in[1];  // [B, N, N]
    const float* Wm   = (const float*)d_in[2];  // [H, H]
    const float* bias = (const float*)d_in[3];  // [B, H]
    float* out = (float*)d_out;                 // [B, H]

    rowsum_kernel<<<(BATCH * NN) / 8, 256>>>(adj);
    weight_kernel<<<(BATCH * NN + 255) / 256, 256>>>(adj);
    reduce_kernel<<<(BATCH * HID) / 8, 256>>>(feat);
    dim3 g4(BATCH, HCHUNKS);
    gemv_part_kernel<<<g4, 256>>>(Wm);
    finish_kernel<<<(BATCH * HID + 255) / 256, 256>>>(bias, out);
}

// round 6
// speedup vs baseline: 1.2561x; 1.0688x over previous
#include <cuda_runtime.h>
#include <math.h>

#define BATCH 16
#define HID   512
#define NN    2048

#define KBLK   128              // threads per block = k-values per block
#define KCH    (HID / KBLK)     // 4 k-chunks
#define HCH    32               // h-chunks
#define HPER   (HID / HCH)      // 16 h per chunk

// Scratch (allocation-free rule: __device__ globals)
__device__ float g_d[BATCH * NN];            // d[b,m] = rsqrt(rowsum)
__device__ float g_w[BATCH * NN];            // w[b,m]
__device__ float g_y[BATCH * HID];           // y[b,h]
__device__ float g_part[HCH * BATCH * HID];  // partial GEMV sums

// ---------------------------------------------------------------------------
// Kernel 1: per-row sums of clip(adj,0) (+1 diagonal), store rsqrt.
// One warp per row; fully-coalesced float4 loads, 16 independent loads/lane.
// ---------------------------------------------------------------------------
__global__ void rowsum_kernel(const float* __restrict__ adj) {
    int warp = (blockIdx.x * blockDim.x + threadIdx.x) >> 5;
    int lane = threadIdx.x & 31;
    if (warp >= BATCH * NN) return;

    const float4* row = (const float4*)(adj + (size_t)warp * NN);
    float s = 0.f;
#pragma unroll
    for (int i = 0; i < NN / (4 * 32); ++i) {
        float4 v = row[lane + i * 32];
        s += fmaxf(v.x, 0.f) + fmaxf(v.y, 0.f) + fmaxf(v.z, 0.f) + fmaxf(v.w, 0.f);
    }
#pragma unroll
    for (int o = 16; o; o >>= 1) s += __shfl_xor_sync(0xffffffffu, s, o);
    if (lane == 0) g_d[warp] = rsqrtf(s + 1.0f);
}

// ---------------------------------------------------------------------------
// Kernel 2 (tiny): w[b,m] = d[b,0] * (clip(adj[b,0,m],0) + [m==0]) * d[b,m]
// ---------------------------------------------------------------------------
__global__ void weight_kernel(const float* __restrict__ adj) {
    int idx = blockIdx.x * blockDim.x + threadIdx.x;
    if (idx >= BATCH * NN) return;
    int b = idx / NN;
    int m = idx - b * NN;
    float a = fmaxf(adj[(size_t)b * NN * NN + m], 0.f) + (m == 0 ? 1.0f : 0.0f);
    g_w[idx] = g_d[b * NN] * a * g_d[idx];
}

// ---------------------------------------------------------------------------
// Kernel 3: y[b,h] = dot(w[b,:], feat[b,h,:]). One warp per (b,h).
// ---------------------------------------------------------------------------
__global__ void reduce_kernel(const float* __restrict__ feat) {
    int warp = (blockIdx.x * blockDim.x + threadIdx.x) >> 5;
    int lane = threadIdx.x & 31;
    if (warp >= BATCH * HID) return;
    int b = warp / HID;

    const float4* f  = (const float4*)(feat + (size_t)warp * NN);
    const float4* wp = (const float4*)(g_w + b * NN);
    float s = 0.f;
#pragma unroll
    for (int i = 0; i < NN / (4 * 32); ++i) {
        float4 fv = f[lane + i * 32];
        float4 wv = wp[lane + i * 32];
        s += fv.x * wv.x + fv.y * wv.y + fv.z * wv.z + fv.w * wv.w;
    }
#pragma unroll
    for (int o = 16; o; o >>= 1) s += __shfl_xor_sync(0xffffffffu, s, o);
    if (lane == 0) g_y[warp] = s;
}

// ---------------------------------------------------------------------------
// Kernel 4a: batch-shared GEMV partials. grid=(KCH, HCH)=128 blocks, 128 thr.
// Thread t in block (kc,hc) owns k = kc*128+t; holds ALL 16 batch
// accumulators in registers, so each W[h,k] load feeds 16 independent FMAs.
// W read exactly once total (1 MB). 16-wide ILP hides load latency.
// part[hc][b][k] = sum_{h in chunk hc} y[b,h] * W[h,k]
// ---------------------------------------------------------------------------
__global__ void gemv_part_kernel(const float* __restrict__ Wmat) {
    __shared__ float ys[BATCH * HPER];  // y[b][h-in-chunk], 256 floats
    int kc = blockIdx.x;
    int hc = blockIdx.y;
    int t  = threadIdx.x;
    int k  = kc * KBLK + t;

    for (int i = t; i < BATCH * HPER; i += KBLK) {
        int b = i / HPER, h = i - b * HPER;
        ys[i] = g_y[b * HID + hc * HPER + h];
    }
    __syncthreads();

    float acc[BATCH];
#pragma unroll
    for (int b = 0; b < BATCH; ++b) acc[b] = 0.f;

#pragma unroll
    for (int h = 0; h < HPER; ++h) {
        float w = Wmat[(size_t)(hc * HPER + h) * HID + k];  // coalesced
#pragma unroll
        for (int b = 0; b < BATCH; ++b)
            acc[b] = fmaf(ys[b * HPER + h], w, acc[b]);
    }

#pragma unroll
    for (int b = 0; b < BATCH; ++b)
        g_part[(size_t)(hc * BATCH + b) * HID + k] = acc[b];  // coalesced
}

// ---------------------------------------------------------------------------
// Kernel 4b: sum the 32 partials + bias, tanh, write. 8192 threads.
// ---------------------------------------------------------------------------
__global__ void finish_kernel(const float* __restrict__ bias,
                              float* __restrict__ out) {
    int idx = blockIdx.x * blockDim.x + threadIdx.x;  // b*HID + k
    if (idx >= BATCH * HID) return;
    float acc = bias[idx];
#pragma unroll
    for (int c = 0; c < HCH; ++c)
        acc += g_part[c * (BATCH * HID) + idx];
    out[idx] = tanhf(acc);
}

// ---------------------------------------------------------------------------
extern "C" void kernel_launch(void* const* d_in, const int* in_sizes, int n_in,
                              void* d_out, int out_size) {
    const float* feat = (const float*)d_in[0];  // [B, H, N]
    const float* adj  = (const float*)d_in[1];  // [B, N, N]
    const float* Wm   = (const float*)d_in[2];  // [H, H]
    const float* bias = (const float*)d_in[3];  // [B, H]
    float* out = (float*)d_out;                 // [B, H]

    rowsum_kernel<<<(BATCH * NN) / 8, 256>>>(adj);
    weight_kernel<<<(BATCH * NN + 255) / 256, 256>>>(adj);
    reduce_kernel<<<(BATCH * HID) / 8, 256>>>(feat);
    dim3 g4(KCH, HCH);
    gemv_part_kernel<<<g4, KBLK>>>(Wm);
    finish_kernel<<<(BATCH * HID + 255) / 256, 256>>>(bias, out);
}